// round 1
// baseline (speedup 1.0000x reference)
#include <cuda_runtime.h>

// ---------------------------------------------------------------------------
// QuantumNeuralNetwork: fused MLP -> 4-qubit circuit -> classifier
//
// Quantum reformulation: state after per-sample RY embedding is a REAL product
// state v = kron_i (cos(f_i/2), sin(f_i/2)). The variational layers + CZ form
// a fixed 16x16 unitary U (depends only on qweights). <Z0> = v^T M v with
// M = Re(U^H Z0 U), a fixed real symmetric matrix computed by a prelude kernel.
// ---------------------------------------------------------------------------

__device__ float g_M[256];   // Re(U^H Z0 U), 16x16

// -------------------- prelude: build M from qweights -----------------------
__global__ void build_M_kernel(const float* __restrict__ qw /* [2][4][3] */) {
    __shared__ float Ur[16][16];
    __shared__ float Ui[16][16];
    int t = threadIdx.x;               // 256 threads

    {   int z = t >> 4, c = t & 15;
        Ur[z][c] = (z == c) ? 1.0f : 0.0f;
        Ui[z][c] = 0.0f; }
    __syncthreads();

    for (int l = 0; l < 2; l++) {
        for (int i = 0; i < 4; i++) {
            float phi   = qw[(l * 4 + i) * 3 + 0];
            float theta = qw[(l * 4 + i) * 3 + 1];
            float omega = qw[(l * 4 + i) * 3 + 2];
            float ct, st;  sincosf(0.5f * theta, &st, &ct);
            float ap = 0.5f * (phi + omega), am = 0.5f * (phi - omega);
            float cap, sap, cam, sam;
            sincosf(ap, &sap, &cap);
            sincosf(am, &sam, &cam);
            // Rot = RZ(omega) RY(theta) RZ(phi)
            float g00r =  cap * ct, g00i = -sap * ct;
            float g01r = -cam * st, g01i = -sam * st;
            float g10r =  cam * st, g10i = -sam * st;
            float g11r =  cap * ct, g11i =  sap * ct;

            int p = 3 - i;             // qubit i -> bit (3-i), z = q0*8+q1*4+q2*2+q3
            int mask = 1 << p;
            if (t < 128) {
                int pr = t >> 4, c = t & 15;
                int z0 = ((pr >> p) << (p + 1)) | (pr & (mask - 1));
                int z1 = z0 | mask;
                float ar = Ur[z0][c], ai = Ui[z0][c];
                float br = Ur[z1][c], bi = Ui[z1][c];
                Ur[z0][c] = g00r * ar - g00i * ai + g01r * br - g01i * bi;
                Ui[z0][c] = g00r * ai + g00i * ar + g01r * bi + g01i * br;
                Ur[z1][c] = g10r * ar - g10i * ai + g11r * br - g11i * bi;
                Ui[z1][c] = g10r * ai + g10i * ar + g11r * bi + g11i * br;
            }
            __syncthreads();
        }
        // CZ chain on (0,1),(1,2),(2,3): diagonal signs, fold into one pass
        {   int z = t >> 4, c = t & 15;
            int neg = 0;
            for (int i = 0; i < 3; i++) {
                int mA = 1 << (3 - i), mB = 1 << (2 - i);
                if ((z & mA) && (z & mB)) neg ^= 1;
            }
            if (neg) { Ur[z][c] = -Ur[z][c]; Ui[z][c] = -Ui[z][c]; } }
        __syncthreads();
    }

    // M[a][b] = sum_z d(z) * Re(conj(U[z][a]) * U[z][b]),  d = +1 if q0=0 else -1
    {   int a = t >> 4, b = t & 15;
        float m = 0.0f;
        #pragma unroll
        for (int z = 0; z < 16; z++) {
            float d = (z & 8) ? -1.0f : 1.0f;
            m += d * (Ur[z][a] * Ur[z][b] + Ui[z][a] * Ui[z][b]);
        }
        g_M[a * 16 + b] = m; }
}

// -------------------- main fused kernel ------------------------------------
__global__ __launch_bounds__(128, 3)
void qnn_kernel(const float* __restrict__ text, const float* __restrict__ image,
                const float* __restrict__ tW1, const float* __restrict__ tb1,
                const float* __restrict__ tW2, const float* __restrict__ tb2,
                const float* __restrict__ iW1, const float* __restrict__ ib1,
                const float* __restrict__ iW2, const float* __restrict__ ib2,
                const float* __restrict__ cW1, const float* __restrict__ cb1,
                const float* __restrict__ cW2, const float* __restrict__ cb2,
                float* __restrict__ out, int B)
{
    __shared__ float s_tW1[512];     // [16][32]
    __shared__ float s_tW2[128];     // [32][4]
    __shared__ float s_iW1[3072];    // [48][64]
    __shared__ float s_iW2[256];     // [64][4]
    __shared__ float s_tb1[32], s_ib1[64];
    __shared__ float s_M[256];
    __shared__ float s_cW1[16], s_cb1[16], s_cW2[32];
    __shared__ float s_fb[4];        // tb2 + ib2
    __shared__ float s_cb2[2];

    int tid = threadIdx.x;
    for (int i = tid; i < 512;  i += 128) s_tW1[i] = tW1[i];
    for (int i = tid; i < 3072; i += 128) s_iW1[i] = iW1[i];
    for (int i = tid; i < 256;  i += 128) { s_iW2[i] = iW2[i]; s_M[i] = g_M[i]; }
    if (tid < 128) s_tW2[tid] = tW2[tid];
    if (tid < 64)  s_ib1[tid] = ib1[tid];
    if (tid < 32)  { s_tb1[tid] = tb1[tid]; s_cW2[tid] = cW2[tid]; }
    if (tid < 16)  { s_cW1[tid] = cW1[tid]; s_cb1[tid] = cb1[tid]; }
    if (tid < 4)   s_fb[tid] = tb2[tid] + ib2[tid];
    if (tid < 2)   s_cb2[tid] = cb2[tid];
    __syncthreads();

    int sidx = blockIdx.x * 128 + tid;
    if (sidx >= B) return;

    float feats[4];
    #pragma unroll
    for (int c = 0; c < 4; c++) feats[c] = s_fb[c];

    // ---- image MLP: 48 -> relu(64) -> 4 (dominant cost) ----
    {
        float acc[64];
        #pragma unroll
        for (int j = 0; j < 64; j++) acc[j] = s_ib1[j];
        const float4* ip = reinterpret_cast<const float4*>(image) + (size_t)sidx * 12;
        for (int kk = 0; kk < 12; kk++) {
            float4 a4 = __ldg(ip + kk);
            float av[4] = {a4.x, a4.y, a4.z, a4.w};
            #pragma unroll
            for (int dk = 0; dk < 4; dk++) {
                const float* wrow = &s_iW1[(kk * 4 + dk) * 64];
                float a = av[dk];
                #pragma unroll
                for (int j = 0; j < 64; j++) acc[j] = fmaf(a, wrow[j], acc[j]);
            }
        }
        #pragma unroll
        for (int j = 0; j < 64; j++) {
            float h = fmaxf(acc[j], 0.0f);
            #pragma unroll
            for (int c = 0; c < 4; c++) feats[c] = fmaf(h, s_iW2[j * 4 + c], feats[c]);
        }
    }

    // ---- text MLP: 16 -> relu(32) -> 4 ----
    {
        float acc[32];
        #pragma unroll
        for (int j = 0; j < 32; j++) acc[j] = s_tb1[j];
        const float4* tp = reinterpret_cast<const float4*>(text) + (size_t)sidx * 4;
        #pragma unroll
        for (int kk = 0; kk < 4; kk++) {
            float4 a4 = __ldg(tp + kk);
            float av[4] = {a4.x, a4.y, a4.z, a4.w};
            #pragma unroll
            for (int dk = 0; dk < 4; dk++) {
                const float* wrow = &s_tW1[(kk * 4 + dk) * 32];
                float a = av[dk];
                #pragma unroll
                for (int j = 0; j < 32; j++) acc[j] = fmaf(a, wrow[j], acc[j]);
            }
        }
        #pragma unroll
        for (int j = 0; j < 32; j++) {
            float h = fmaxf(acc[j], 0.0f);
            #pragma unroll
            for (int c = 0; c < 4; c++) feats[c] = fmaf(h, s_tW2[j * 4 + c], feats[c]);
        }
    }

    // ---- quantum: <Z0> = v^T M v, v = kron of (cos, sin) pairs ----
    // ref: feats_ref = (tf+imf)*0.5, half-angle -> (tf+imf)*0.25
    float cq[4], sq[4];
    #pragma unroll
    for (int i = 0; i < 4; i++) sincosf(feats[i] * 0.25f, &sq[i], &cq[i]);
    float p0[4] = {cq[0]*cq[1], cq[0]*sq[1], sq[0]*cq[1], sq[0]*sq[1]};
    float p1[4] = {cq[2]*cq[3], cq[2]*sq[3], sq[2]*cq[3], sq[2]*sq[3]};
    float v[16];
    #pragma unroll
    for (int h = 0; h < 4; h++)
        #pragma unroll
        for (int lo = 0; lo < 4; lo++) v[h * 4 + lo] = p0[h] * p1[lo];

    float q = 0.0f;
    #pragma unroll
    for (int a = 0; a < 16; a++) {
        float w = 0.0f;
        #pragma unroll
        for (int b = 0; b < 16; b++) w = fmaf(s_M[a * 16 + b], v[b], w);
        q = fmaf(v[a], w, q);
    }

    // ---- classifier: 1 -> relu(16) -> 2 ----
    float o0 = s_cb2[0], o1 = s_cb2[1];
    #pragma unroll
    for (int j = 0; j < 16; j++) {
        float h = fmaxf(fmaf(q, s_cW1[j], s_cb1[j]), 0.0f);
        o0 = fmaf(h, s_cW2[j * 2 + 0], o0);
        o1 = fmaf(h, s_cW2[j * 2 + 1], o1);
    }
    float2 r; r.x = o0; r.y = o1;
    reinterpret_cast<float2*>(out)[sidx] = r;
}

// -------------------- launch -----------------------------------------------
extern "C" void kernel_launch(void* const* d_in, const int* in_sizes, int n_in,
                              void* d_out, int out_size) {
    const float* text = (const float*)d_in[0];
    const float* image= (const float*)d_in[1];
    const float* tW1  = (const float*)d_in[2];
    const float* tb1  = (const float*)d_in[3];
    const float* tW2  = (const float*)d_in[4];
    const float* tb2  = (const float*)d_in[5];
    const float* iW1  = (const float*)d_in[6];
    const float* ib1  = (const float*)d_in[7];
    const float* iW2  = (const float*)d_in[8];
    const float* ib2  = (const float*)d_in[9];
    const float* qw   = (const float*)d_in[10];
    const float* cW1  = (const float*)d_in[11];
    const float* cb1  = (const float*)d_in[12];
    const float* cW2  = (const float*)d_in[13];
    const float* cb2  = (const float*)d_in[14];
    float* out = (float*)d_out;

    int B = in_sizes[0] / 16;

    build_M_kernel<<<1, 256>>>(qw);
    int nblk = (B + 127) / 128;
    qnn_kernel<<<nblk, 128>>>(text, image, tW1, tb1, tW2, tb2,
                              iW1, ib1, iW2, ib2, cW1, cb1, cW2, cb2,
                              out, B);
}